// round 8
// baseline (speedup 1.0000x reference)
#include <cuda_runtime.h>
#include <cstdint>

#define B_SZ   8192
#define K_DIM  1024
#define V_N    2
#define BT     32      // batch rows per CTA
#define PP     64      // panel width
#define KC     32      // k-chunk
#define NTH    256     // 8 warps
#define NPAN   (K_DIM / PP)
#define UR     (2*BT + 4)   // 68 floats, rows 16B-aligned
#define AR     (PP + 4)     // 68

// -------- packed f32x2 helpers (B300 FFMA2 path, PTX-only) --------
__device__ __forceinline__ unsigned long long pack2(float x) {
    unsigned long long r;
    unsigned int u = __float_as_uint(x);
    asm("mov.b64 %0, {%1, %1};" : "=l"(r) : "r"(u));
    return r;
}
__device__ __forceinline__ unsigned long long ffma2(unsigned long long a,
                                                    unsigned long long b,
                                                    unsigned long long c) {
    unsigned long long d;
    asm("fma.rn.f32x2 %0, %1, %2, %3;" : "=l"(d) : "l"(a), "l"(b), "l"(c));
    return d;
}

// GEMM-phase (double-buffered) and solve-phase smem alias (phases sync-separated)
union SMem {
    struct {
        float u_dup[2][KC][UR];   // u_dup[s][k][2b..2b+1] = u[b]   (17.4 KB)
        float a_s[2][KC][AR];     // a_s[s][k][jj] = A[j0+jj][kb*KC+k] (17.4 KB)
    } g;
    struct {
        float diag[PP][AR];       // diag[i][jj] = A[j0+jj][j0+i], 0 unless i<jj
        float up[BT][AR];         // panel values
    } m;
};  // 34.8 KB -> 2 CTAs/SM = 69.6 KB

__global__ void __launch_bounds__(NTH, 2)
scm_kernel(const float* __restrict__ z,
           const int*   __restrict__ tgt,
           const int*   __restrict__ vari,
           const float* __restrict__ A,
           const float* __restrict__ means,
           const float* __restrict__ logsc,
           float*       __restrict__ out)
{
    __shared__ __align__(16) SMem sm;

    const int tid  = threadIdx.x;
    const int b0   = blockIdx.x * BT;
    const int lane = tid & 31;
    const int warp = tid >> 5;
    // warp-local tiling: each warp = 4 row-groups x 8 col-groups
    // per k: a-load 8x16B=128B (1 wavefront), u-loads 4x16B=64B broadcast-heavy
    const int jg = (lane & 7) | ((warp & 1) << 3);    // 0..15 -> cols 4jg..4jg+3
    const int rg = (lane >> 3) | ((warp >> 1) << 2);  // 0..15 -> rows 2rg, 2rg+1

    // ---- per-sample intervention scalar (threads 0..31) ----
    int   t_abs = -(1 << 30);
    float vint  = 0.0f;
    if (tid < BT) {
        const int b = b0 + tid;
        const int t = tgt[b];
        if (t >= 0) {
            const int v   = vari[b];
            const float m = means[t * V_N + v];
            const float s = expf(logsc[t * V_N + v]);
            vint  = fmaf(s, z[(size_t)b * K_DIM + t], m);
            t_abs = t;
        }
    }

    // staging coords: u chunk 32x32 -> 1 float4/thread; a chunk 64x32 -> 2
    const int ur_ = tid >> 3;        // 0..31
    const int uc_ = tid & 7;         // 0..7

    for (int p = 0; p < NPAN; ++p) {
        const int j0 = p * PP;

        // ===== GEMM: acc[r][pp] = sum_{k<j0} u[2rg+r][k] * A[j0+4jg+..][k] ====
        unsigned long long acc[2][2];
        acc[0][0] = acc[0][1] = acc[1][0] = acc[1][1] = 0ULL;

        const int nkb = 2 * p;
        if (nkb > 0) {
            float4 ru, ra[2];
            // stage chunk 0 into buffer 0
            ru = *(const float4*)(out + (size_t)(b0 + ur_) * K_DIM + 4 * uc_);
            #pragma unroll
            for (int q = 0; q < 2; ++q) {
                const int f = tid + NTH * q;
                ra[q] = *(const float4*)(A + (size_t)(j0 + (f >> 3)) * K_DIM + 4 * (f & 7));
            }
            {
                const float uv[4] = {ru.x, ru.y, ru.z, ru.w};
                #pragma unroll
                for (int j = 0; j < 4; ++j)
                    *(unsigned long long*)&sm.g.u_dup[0][4*uc_ + j][2*ur_] = pack2(uv[j]);
                #pragma unroll
                for (int q = 0; q < 2; ++q) {
                    const int f = tid + NTH * q;
                    const int r = f >> 3, c = f & 7;
                    const float av[4] = {ra[q].x, ra[q].y, ra[q].z, ra[q].w};
                    #pragma unroll
                    for (int j = 0; j < 4; ++j)
                        sm.g.a_s[0][4*c + j][r] = av[j];
                }
            }
            __syncthreads();

            for (int kb = 0; kb < nkb; ++kb) {
                const bool more = (kb + 1 < nkb);
                if (more) {
                    ru = *(const float4*)(out + (size_t)(b0 + ur_) * K_DIM + (kb + 1) * KC + 4 * uc_);
                    #pragma unroll
                    for (int q = 0; q < 2; ++q) {
                        const int f = tid + NTH * q;
                        ra[q] = *(const float4*)(A + (size_t)(j0 + (f >> 3)) * K_DIM + (kb + 1) * KC + 4 * (f & 7));
                    }
                }
                const int s = kb & 1;
                const float* ub = &sm.g.u_dup[s][0][4 * rg];
                const float* ab = &sm.g.a_s[s][0][4 * jg];
                #pragma unroll 4
                for (int k = 0; k < KC; ++k) {
                    const ulonglong2 u01 = *(const ulonglong2*)(ub + k * UR);
                    const ulonglong2 bp  = *(const ulonglong2*)(ab + k * AR);
                    acc[0][0] = ffma2(u01.x, bp.x, acc[0][0]);
                    acc[0][1] = ffma2(u01.x, bp.y, acc[0][1]);
                    acc[1][0] = ffma2(u01.y, bp.x, acc[1][0]);
                    acc[1][1] = ffma2(u01.y, bp.y, acc[1][1]);
                }
                if (more) {
                    const int ns = s ^ 1;
                    const float uv[4] = {ru.x, ru.y, ru.z, ru.w};
                    #pragma unroll
                    for (int j = 0; j < 4; ++j)
                        *(unsigned long long*)&sm.g.u_dup[ns][4*uc_ + j][2*ur_] = pack2(uv[j]);
                    #pragma unroll
                    for (int q = 0; q < 2; ++q) {
                        const int f = tid + NTH * q;
                        const int r = f >> 3, c = f & 7;
                        const float av[4] = {ra[q].x, ra[q].y, ra[q].z, ra[q].w};
                        #pragma unroll
                        for (int j = 0; j < 4; ++j)
                            sm.g.a_s[ns][4*c + j][r] = av[j];
                    }
                }
                __syncthreads();
            }
        }

        // ========== switch to solve-phase smem (aliases GEMM tiles) ==========
        #pragma unroll
        for (int i = 0; i < 2; ++i) {
            *(unsigned long long*)&sm.m.up[2*rg + i][4*jg]     = acc[i][0];
            *(unsigned long long*)&sm.m.up[2*rg + i][4*jg + 2] = acc[i][1];
        }
        // diagonal block, transposed + strictly-lower masked
        {
            const int jj  = tid & 63;
            const int ig0 = (tid >> 6) * 16;
            const float* src = A + (size_t)(j0 + jj) * K_DIM + j0 + ig0;
            #pragma unroll
            for (int q = 0; q < 4; ++q) {
                const float4 r = *(const float4*)(src + 4 * q);
                const int i = ig0 + 4 * q;
                sm.m.diag[i + 0][jj] = (i + 0 < jj) ? r.x : 0.0f;
                sm.m.diag[i + 1][jj] = (i + 1 < jj) ? r.y : 0.0f;
                sm.m.diag[i + 2][jj] = (i + 2 < jj) ? r.z : 0.0f;
                sm.m.diag[i + 3][jj] = (i + 3 < jj) ? r.w : 0.0f;
            }
        }
        __syncthreads();

        // ======= in-panel sequential micro-solve: thread b owns a sample =====
        if (tid < BT) {
            float ul[PP];
            const float* zp = z + (size_t)(b0 + tid) * K_DIM + j0;
            #pragma unroll
            for (int q = 0; q < 16; ++q) {
                const float4 zq = *(const float4*)(zp + 4 * q);
                const float4 aq = *(const float4*)&sm.m.up[tid][4 * q];
                ul[4*q+0] = aq.x + zq.x;
                ul[4*q+1] = aq.y + zq.y;
                ul[4*q+2] = aq.z + zq.z;
                ul[4*q+3] = aq.w + zq.w;
            }
            const int jrel = t_abs - j0;
            #pragma unroll
            for (int i = 0; i < PP; ++i) {
                const float val = (jrel == i) ? vint : ul[i];
                ul[i] = val;
                #pragma unroll
                for (int q = (i >> 2); q < 16; ++q) {
                    const float4 d = *(const float4*)&sm.m.diag[i][4 * q];
                    ul[4*q+0] = fmaf(d.x, val, ul[4*q+0]);
                    ul[4*q+1] = fmaf(d.y, val, ul[4*q+1]);
                    ul[4*q+2] = fmaf(d.z, val, ul[4*q+2]);
                    ul[4*q+3] = fmaf(d.w, val, ul[4*q+3]);
                }
            }
            #pragma unroll
            for (int q = 0; q < 16; ++q) {
                float4 v;
                v.x = ul[4*q+0]; v.y = ul[4*q+1]; v.z = ul[4*q+2]; v.w = ul[4*q+3];
                *(float4*)&sm.m.up[tid][4 * q] = v;
            }
        }
        __syncthreads();

        // ---- coalesced panel writeout (out doubles as u-scratch) ----
        {
            const int r0 = tid >> 4;          // 0..15
            const int c0 = (tid & 15) * 4;    // 0..60
            #pragma unroll
            for (int pass = 0; pass < 2; ++pass) {
                const int row = pass * 16 + r0;
                const float4 v = *(const float4*)&sm.m.up[row][c0];
                *(float4*)(out + (size_t)(b0 + row) * K_DIM + j0 + c0) = v;
            }
        }
        __syncthreads();
    }
}

extern "C" void kernel_launch(void* const* d_in, const int* in_sizes, int n_in,
                              void* d_out, int out_size) {
    const float* z     = (const float*)d_in[0];
    const int*   tgt   = (const int*)  d_in[1];
    const int*   vari  = (const int*)  d_in[2];
    const float* A     = (const float*)d_in[3];
    const float* means = (const float*)d_in[4];
    const float* logsc = (const float*)d_in[5];
    float* out = (float*)d_out;
    (void)in_sizes; (void)n_in; (void)out_size;

    scm_kernel<<<B_SZ / BT, NTH>>>(z, tgt, vari, A, means, logsc, out);
}

// round 13
// speedup vs baseline: 2.3201x; 2.3201x over previous
#include <cuda_runtime.h>
#include <cuda_bf16.h>
#include <cstdint>

#define B_SZ   8192
#define K_DIM  1024
#define V_N    2
#define BT     64      // batch rows per CTA (= GEMM M)
#define PP     64      // panel width (= GEMM N)
#define KC     32      // k per chunk (2 mma k-steps of 16)
#define NTH    256     // 8 warps: 4 (m) x 2 (n)
#define NPAN   (K_DIM / PP)
#define AR     68      // f32 row stride (diag/up)
#define TR     40      // bf16 row stride for gemm tiles (32 + 8 pad -> 80B rows)

// ---------------- global scratch (__device__ arrays are allowed) -------------
__device__ __nv_bfloat16 g_uhi[B_SZ * K_DIM];
__device__ __nv_bfloat16 g_ulo[B_SZ * K_DIM];
__device__ __nv_bfloat16 g_ahi[K_DIM * K_DIM];
__device__ __nv_bfloat16 g_alo[K_DIM * K_DIM];

// GEMM-phase (double-buffered hi/lo tiles) aliases solve-phase (diag/up)
union SMem {
    struct {
        __nv_bfloat16 u[2][2][64][TR];   // [buf][hi/lo][row][k]  20480 B
        __nv_bfloat16 a[2][2][64][TR];   //                        20480 B
    } g;
    struct {
        float diag[PP][AR];              // 17408 B
        float up[BT][AR];                // 17408 B
    } m;
};
#define OFF_U(s,h) (uint32_t)((((s)*2 + (h)) * 64 * TR) * 2)
#define OFF_A(s,h) (uint32_t)(20480 + (((s)*2 + (h)) * 64 * TR) * 2)

// -------- HMMA helpers (baseline PTX: works on plain sm_103 target) ---------
__device__ __forceinline__ void ldsm4(uint32_t& r0, uint32_t& r1,
                                      uint32_t& r2, uint32_t& r3, uint32_t addr) {
    asm volatile("ldmatrix.sync.aligned.m8n8.x4.shared.b16 {%0,%1,%2,%3}, [%4];"
                 : "=r"(r0), "=r"(r1), "=r"(r2), "=r"(r3) : "r"(addr));
}
__device__ __forceinline__ void mma_bf16(float& d0, float& d1, float& d2, float& d3,
                                         uint32_t a0, uint32_t a1, uint32_t a2, uint32_t a3,
                                         uint32_t b0, uint32_t b1) {
    asm volatile("mma.sync.aligned.m16n8k16.row.col.f32.bf16.bf16.f32 "
                 "{%0,%1,%2,%3},{%4,%5,%6,%7},{%8,%9},{%0,%1,%2,%3};"
                 : "+f"(d0), "+f"(d1), "+f"(d2), "+f"(d3)
                 : "r"(a0), "r"(a1), "r"(a2), "r"(a3), "r"(b0), "r"(b1));
}

// ---------------- prep: split A into bf16 hi/lo ----------------
__global__ void prep_kernel(const float* __restrict__ A) {
    const int i = blockIdx.x * blockDim.x + threadIdx.x;
    const float x = A[i];
    const __nv_bfloat16 h = __float2bfloat16(x);
    g_ahi[i] = h;
    g_alo[i] = __float2bfloat16(x - __bfloat162float(h));
}

// ---------------- main kernel ----------------
__global__ void __launch_bounds__(NTH)
scm_kernel(const float* __restrict__ z,
           const int*   __restrict__ tgt,
           const int*   __restrict__ vari,
           const float* __restrict__ A,
           const float* __restrict__ means,
           const float* __restrict__ logsc,
           float*       __restrict__ out)
{
    __shared__ __align__(16) SMem sm;
    const uint32_t sbase = (uint32_t)__cvta_generic_to_shared(&sm);

    const int tid  = threadIdx.x;
    const int lane = tid & 31;
    const int warp = tid >> 5;
    const int b0   = blockIdx.x * BT;
    const int wrow = warp & 3;        // m-tile: rows wrow*16 .. +15
    const int wcol = warp >> 2;       // n-half: cols wcol*32 .. +31

    // ldmatrix lane byte-offsets within a [64][TR] bf16 tile
    const int lg = lane >> 3, lr = lane & 7;
    const uint32_t laneA  = (uint32_t)(((wrow * 16 + lr + (lg & 1) * 8) * TR + (lg >> 1) * 8) * 2);
    const uint32_t laneB0 = (uint32_t)(((wcol * 32 + lr + (lg >> 1) * 8) * TR + (lg & 1) * 8) * 2);
    const uint32_t laneB1 = laneB0 + 16 * TR * 2;

    // staging coords: tile 64 rows x 32 bf16 = 256 x 16B
    const int srow = tid >> 2, sc = tid & 3;

    // ---- per-sample intervention scalar (threads 0..63) ----
    int   t_abs = -(1 << 30);
    float vint  = 0.0f;
    if (tid < BT) {
        const int b = b0 + tid;
        const int t = tgt[b];
        if (t >= 0) {
            const int v   = vari[b];
            const float m = means[t * V_N + v];
            const float s = expf(logsc[t * V_N + v]);
            vint  = fmaf(s, z[(size_t)b * K_DIM + t], m);
            t_abs = t;
        }
    }

    for (int p = 0; p < NPAN; ++p) {
        const int j0  = p * PP;
        const int nkb = 2 * p;

        float acc[4][4];
        #pragma unroll
        for (int i = 0; i < 4; ++i)
            #pragma unroll
            for (int j = 0; j < 4; ++j) acc[i][j] = 0.0f;

        if (nkb > 0) {
            uint4 ruh, rul, rah, ral;
            // stage chunk 0 into buffer 0
            {
                const size_t gu = (size_t)(b0 + srow) * K_DIM + sc * 8;
                const size_t ga = (size_t)(j0 + srow) * K_DIM + sc * 8;
                ruh = *(const uint4*)(g_uhi + gu);
                rul = *(const uint4*)(g_ulo + gu);
                rah = *(const uint4*)(g_ahi + ga);
                ral = *(const uint4*)(g_alo + ga);
                *(uint4*)&sm.g.u[0][0][srow][sc * 8] = ruh;
                *(uint4*)&sm.g.u[0][1][srow][sc * 8] = rul;
                *(uint4*)&sm.g.a[0][0][srow][sc * 8] = rah;
                *(uint4*)&sm.g.a[0][1][srow][sc * 8] = ral;
            }
            __syncthreads();

            for (int kb = 0; kb < nkb; ++kb) {
                const bool more = (kb + 1 < nkb);
                if (more) {
                    const size_t gu = (size_t)(b0 + srow) * K_DIM + (kb + 1) * KC + sc * 8;
                    const size_t ga = (size_t)(j0 + srow) * K_DIM + (kb + 1) * KC + sc * 8;
                    ruh = *(const uint4*)(g_uhi + gu);
                    rul = *(const uint4*)(g_ulo + gu);
                    rah = *(const uint4*)(g_ahi + ga);
                    ral = *(const uint4*)(g_alo + ga);
                }
                const int s = kb & 1;
                const uint32_t buh = sbase + OFF_U(s, 0);
                const uint32_t bul = sbase + OFF_U(s, 1);
                const uint32_t bah = sbase + OFF_A(s, 0);
                const uint32_t bal = sbase + OFF_A(s, 1);
                #pragma unroll
                for (int st = 0; st < 2; ++st) {
                    const uint32_t ko = st * 32;   // 16 bf16 = 32B
                    uint32_t ah[4], al[4], bh[8], bl[8];
                    ldsm4(ah[0], ah[1], ah[2], ah[3], buh + laneA + ko);
                    ldsm4(al[0], al[1], al[2], al[3], bul + laneA + ko);
                    ldsm4(bh[0], bh[1], bh[2], bh[3], bah + laneB0 + ko);
                    ldsm4(bh[4], bh[5], bh[6], bh[7], bah + laneB1 + ko);
                    ldsm4(bl[0], bl[1], bl[2], bl[3], bal + laneB0 + ko);
                    ldsm4(bl[4], bl[5], bl[6], bl[7], bal + laneB1 + ko);
                    #pragma unroll
                    for (int ln = 0; ln < 4; ++ln) {
                        mma_bf16(acc[ln][0], acc[ln][1], acc[ln][2], acc[ln][3],
                                 ah[0], ah[1], ah[2], ah[3], bh[2*ln], bh[2*ln+1]);
                        mma_bf16(acc[ln][0], acc[ln][1], acc[ln][2], acc[ln][3],
                                 ah[0], ah[1], ah[2], ah[3], bl[2*ln], bl[2*ln+1]);
                        mma_bf16(acc[ln][0], acc[ln][1], acc[ln][2], acc[ln][3],
                                 al[0], al[1], al[2], al[3], bh[2*ln], bh[2*ln+1]);
                    }
                }
                if (more) {
                    const int ns = s ^ 1;
                    *(uint4*)&sm.g.u[ns][0][srow][sc * 8] = ruh;
                    *(uint4*)&sm.g.u[ns][1][srow][sc * 8] = rul;
                    *(uint4*)&sm.g.a[ns][0][srow][sc * 8] = rah;
                    *(uint4*)&sm.g.a[ns][1][srow][sc * 8] = ral;
                }
                __syncthreads();
            }
        }

        // ========== switch to solve-phase smem (aliases GEMM tiles) ==========
        // epilogue: mma fragments -> up  (d0,d1 at (r, 2c0), d2,d3 at (r+8, 2c0))
        {
            const int er = wrow * 16 + (lane >> 2);
            const int ec = wcol * 32 + 2 * (lane & 3);
            #pragma unroll
            for (int ln = 0; ln < 4; ++ln) {
                float2 v0; v0.x = acc[ln][0]; v0.y = acc[ln][1];
                float2 v1; v1.x = acc[ln][2]; v1.y = acc[ln][3];
                *(float2*)&sm.m.up[er][ec + ln * 8]     = v0;
                *(float2*)&sm.m.up[er + 8][ec + ln * 8] = v1;
            }
        }
        // diagonal block, transposed + strictly-lower masked
        {
            const int jj  = tid & 63;
            const int ig0 = (tid >> 6) * 16;
            const float* src = A + (size_t)(j0 + jj) * K_DIM + j0 + ig0;
            #pragma unroll
            for (int q = 0; q < 4; ++q) {
                const float4 r = *(const float4*)(src + 4 * q);
                const int i = ig0 + 4 * q;
                sm.m.diag[i + 0][jj] = (i + 0 < jj) ? r.x : 0.0f;
                sm.m.diag[i + 1][jj] = (i + 1 < jj) ? r.y : 0.0f;
                sm.m.diag[i + 2][jj] = (i + 2 < jj) ? r.z : 0.0f;
                sm.m.diag[i + 3][jj] = (i + 3 < jj) ? r.w : 0.0f;
            }
        }
        __syncthreads();

        // ======= in-panel sequential micro-solve: thread b owns a sample =====
        if (tid < BT) {
            float ul[PP];
            const float* zp = z + (size_t)(b0 + tid) * K_DIM + j0;
            #pragma unroll
            for (int q = 0; q < 16; ++q) {
                const float4 zq = *(const float4*)(zp + 4 * q);
                const float4 aq = *(const float4*)&sm.m.up[tid][4 * q];
                ul[4*q+0] = aq.x + zq.x;
                ul[4*q+1] = aq.y + zq.y;
                ul[4*q+2] = aq.z + zq.z;
                ul[4*q+3] = aq.w + zq.w;
            }
            const int jrel = t_abs - j0;
            #pragma unroll
            for (int i = 0; i < PP; ++i) {
                const float val = (jrel == i) ? vint : ul[i];
                ul[i] = val;
                #pragma unroll
                for (int q = (i >> 2); q < 16; ++q) {
                    const float4 d = *(const float4*)&sm.m.diag[i][4 * q];
                    ul[4*q+0] = fmaf(d.x, val, ul[4*q+0]);
                    ul[4*q+1] = fmaf(d.y, val, ul[4*q+1]);
                    ul[4*q+2] = fmaf(d.z, val, ul[4*q+2]);
                    ul[4*q+3] = fmaf(d.w, val, ul[4*q+3]);
                }
            }
            // fp32 output
            float* op = out + (size_t)(b0 + tid) * K_DIM + j0;
            #pragma unroll
            for (int q = 0; q < 16; ++q) {
                float4 v; v.x = ul[4*q+0]; v.y = ul[4*q+1]; v.z = ul[4*q+2]; v.w = ul[4*q+3];
                *(float4*)(op + 4 * q) = v;
            }
            // bf16 hi/lo scratch for later panels' GEMMs
            __nv_bfloat16* uh  = g_uhi + (size_t)(b0 + tid) * K_DIM + j0;
            __nv_bfloat16* ulp = g_ulo + (size_t)(b0 + tid) * K_DIM + j0;
            #pragma unroll
            for (int q = 0; q < 8; ++q) {
                union { __nv_bfloat16 v[8]; uint4 u; } ph, pl;
                #pragma unroll
                for (int j = 0; j < 8; ++j) {
                    const float x = ul[8*q + j];
                    const __nv_bfloat16 h = __float2bfloat16(x);
                    ph.v[j] = h;
                    pl.v[j] = __float2bfloat16(x - __bfloat162float(h));
                }
                *(uint4*)(uh  + 8 * q) = ph.u;
                *(uint4*)(ulp + 8 * q) = pl.u;
            }
        }
        __syncthreads();   // scratch + smem reuse ordered before next panel
    }
}

extern "C" void kernel_launch(void* const* d_in, const int* in_sizes, int n_in,
                              void* d_out, int out_size) {
    const float* z     = (const float*)d_in[0];
    const int*   tgt   = (const int*)  d_in[1];
    const int*   vari  = (const int*)  d_in[2];
    const float* A     = (const float*)d_in[3];
    const float* means = (const float*)d_in[4];
    const float* logsc = (const float*)d_in[5];
    float* out = (float*)d_out;
    (void)in_sizes; (void)n_in; (void)out_size;

    prep_kernel<<<(K_DIM * K_DIM) / 256, 256>>>(A);
    scm_kernel<<<B_SZ / BT, NTH>>>(z, tgt, vari, A, means, logsc, out);
}

// round 14
// speedup vs baseline: 2.4762x; 1.0673x over previous
#include <cuda_runtime.h>
#include <cuda_bf16.h>
#include <cstdint>

#define B_SZ   8192
#define K_DIM  1024
#define V_N    2
#define BT     64      // batch rows per CTA (= GEMM M)
#define PP     64      // panel width (= GEMM N)
#define KC     64      // k per chunk (4 mma k-steps of 16)
#define NTH    256     // 8 warps: 4 (m) x 2 (n)
#define NPAN   (K_DIM / PP)
#define AR     68      // f32 row stride (diag/up)
#define TRG    72      // bf16 row stride for gemm tiles (64 + 8 pad -> 144B rows)

// ---------------- global scratch (__device__ arrays are allowed) -------------
__device__ __nv_bfloat16 g_uhi[B_SZ * K_DIM];
__device__ __nv_bfloat16 g_ulo[B_SZ * K_DIM];
__device__ __nv_bfloat16 g_ahi[K_DIM * K_DIM];
__device__ __nv_bfloat16 g_alo[K_DIM * K_DIM];

// dynamic smem layout:
//   GEMM phase: 2 buffers x 4 tiles (uhi,ulo,ahi,alo), each [64][TRG] bf16
//   solve phase (aliases): diag [64][AR] f32 @0, up [64][AR] f32 @17408
#define TILE_B   (64 * TRG * 2)                   // 9216 B
#define OFF_T(s,w) (uint32_t)(((s) * 4 + (w)) * TILE_B)
#define SM_BYTES (8 * TILE_B)                     // 73728
#define DIAG_OFF 0
#define UP_OFF   17408

// -------- HMMA helpers (baseline PTX: works on plain sm_103 target) ---------
__device__ __forceinline__ void ldsm4(uint32_t& r0, uint32_t& r1,
                                      uint32_t& r2, uint32_t& r3, uint32_t addr) {
    asm volatile("ldmatrix.sync.aligned.m8n8.x4.shared.b16 {%0,%1,%2,%3}, [%4];"
                 : "=r"(r0), "=r"(r1), "=r"(r2), "=r"(r3) : "r"(addr));
}
__device__ __forceinline__ void mma_bf16(float& d0, float& d1, float& d2, float& d3,
                                         uint32_t a0, uint32_t a1, uint32_t a2, uint32_t a3,
                                         uint32_t b0, uint32_t b1) {
    asm volatile("mma.sync.aligned.m16n8k16.row.col.f32.bf16.bf16.f32 "
                 "{%0,%1,%2,%3},{%4,%5,%6,%7},{%8,%9},{%0,%1,%2,%3};"
                 : "+f"(d0), "+f"(d1), "+f"(d2), "+f"(d3)
                 : "r"(a0), "r"(a1), "r"(a2), "r"(a3), "r"(b0), "r"(b1));
}
__device__ __forceinline__ void cp16(uint32_t saddr, const void* gptr) {
    asm volatile("cp.async.cg.shared.global [%0], [%1], 16;"
                 :: "r"(saddr), "l"(gptr) : "memory");
}
__device__ __forceinline__ void cp_commit() {
    asm volatile("cp.async.commit_group;" ::: "memory");
}
__device__ __forceinline__ void cp_wait0() {
    asm volatile("cp.async.wait_group 0;" ::: "memory");
}

// ---------------- prep: split A into bf16 hi/lo ----------------
__global__ void prep_kernel(const float* __restrict__ A) {
    const int i = blockIdx.x * blockDim.x + threadIdx.x;
    const float x = A[i];
    const __nv_bfloat16 h = __float2bfloat16(x);
    g_ahi[i] = h;
    g_alo[i] = __float2bfloat16(x - __bfloat162float(h));
}

// ---------------- main kernel ----------------
__global__ void __launch_bounds__(NTH)
scm_kernel(const float* __restrict__ z,
           const int*   __restrict__ tgt,
           const int*   __restrict__ vari,
           const float* __restrict__ A,
           const float* __restrict__ means,
           const float* __restrict__ logsc,
           float*       __restrict__ out)
{
    extern __shared__ __align__(16) char smem[];
    const uint32_t sbase = (uint32_t)__cvta_generic_to_shared(smem);

    const int tid  = threadIdx.x;
    const int lane = tid & 31;
    const int warp = tid >> 5;
    const int b0   = blockIdx.x * BT;
    const int wrow = warp & 3;        // m-tile: rows wrow*16 .. +15
    const int wcol = warp >> 2;       // n-half: cols wcol*32 .. +31

    // ldmatrix lane byte-offsets within a [64][TRG] bf16 tile
    const int lg = lane >> 3, lr = lane & 7;
    const uint32_t laneA  = (uint32_t)(((wrow * 16 + lr + (lg & 1) * 8) * TRG + (lg >> 1) * 8) * 2);
    const uint32_t laneB0 = (uint32_t)(((wcol * 32 + lr + (lg >> 1) * 8) * TRG + (lg & 1) * 8) * 2);
    const uint32_t laneB1 = laneB0 + 16 * TRG * 2;

    // ---- per-sample intervention scalar (threads 0..63) ----
    int   t_abs = -(1 << 30);
    float vint  = 0.0f;
    if (tid < BT) {
        const int b = b0 + tid;
        const int t = tgt[b];
        if (t >= 0) {
            const int v   = vari[b];
            const float m = means[t * V_N + v];
            const float s = expf(logsc[t * V_N + v]);
            vint  = fmaf(s, z[(size_t)b * K_DIM + t], m);
            t_abs = t;
        }
    }

    for (int p = 0; p < NPAN; ++p) {
        const int j0  = p * PP;
        const int nkb = p;           // chunks of KC=64

        float accA[4][4], accB[4][4], accC[4][4];
        #pragma unroll
        for (int i = 0; i < 4; ++i)
            #pragma unroll
            for (int j = 0; j < 4; ++j) { accA[i][j] = 0.f; accB[i][j] = 0.f; accC[i][j] = 0.f; }

        if (nkb > 0) {
            // cp.async stage chunk 0 -> buffer 0 (each array: 64 rows x 8 x 16B)
            #pragma unroll
            for (int q = 0; q < 2; ++q) {
                const int slot = tid + NTH * q;
                const int r = slot >> 3, c = slot & 7;
                const uint32_t dof = (uint32_t)((r * TRG + c * 8) * 2);
                const size_t gu = (size_t)(b0 + r) * K_DIM + c * 8;
                const size_t ga = (size_t)(j0 + r) * K_DIM + c * 8;
                cp16(sbase + OFF_T(0,0) + dof, g_uhi + gu);
                cp16(sbase + OFF_T(0,1) + dof, g_ulo + gu);
                cp16(sbase + OFF_T(0,2) + dof, g_ahi + ga);
                cp16(sbase + OFF_T(0,3) + dof, g_alo + ga);
            }
            cp_commit();

            for (int kb = 0; kb < nkb; ++kb) {
                const int s = kb & 1;
                cp_wait0();
                __syncthreads();
                if (kb + 1 < nkb) {
                    const int ns = s ^ 1;
                    #pragma unroll
                    for (int q = 0; q < 2; ++q) {
                        const int slot = tid + NTH * q;
                        const int r = slot >> 3, c = slot & 7;
                        const uint32_t dof = (uint32_t)((r * TRG + c * 8) * 2);
                        const size_t gu = (size_t)(b0 + r) * K_DIM + (kb + 1) * KC + c * 8;
                        const size_t ga = (size_t)(j0 + r) * K_DIM + (kb + 1) * KC + c * 8;
                        cp16(sbase + OFF_T(ns,0) + dof, g_uhi + gu);
                        cp16(sbase + OFF_T(ns,1) + dof, g_ulo + gu);
                        cp16(sbase + OFF_T(ns,2) + dof, g_ahi + ga);
                        cp16(sbase + OFF_T(ns,3) + dof, g_alo + ga);
                    }
                    cp_commit();
                }
                const uint32_t buh = sbase + OFF_T(s,0);
                const uint32_t bul = sbase + OFF_T(s,1);
                const uint32_t bah = sbase + OFF_T(s,2);
                const uint32_t bal = sbase + OFF_T(s,3);
                #pragma unroll
                for (int st = 0; st < 4; ++st) {
                    const uint32_t ko = st * 32;   // 16 bf16 = 32B
                    uint32_t ah[4], al[4], bh[8], bl[8];
                    ldsm4(ah[0], ah[1], ah[2], ah[3], buh + laneA + ko);
                    ldsm4(al[0], al[1], al[2], al[3], bul + laneA + ko);
                    ldsm4(bh[0], bh[1], bh[2], bh[3], bah + laneB0 + ko);
                    ldsm4(bh[4], bh[5], bh[6], bh[7], bah + laneB1 + ko);
                    ldsm4(bl[0], bl[1], bl[2], bl[3], bal + laneB0 + ko);
                    ldsm4(bl[4], bl[5], bl[6], bl[7], bal + laneB1 + ko);
                    #pragma unroll
                    for (int ln = 0; ln < 4; ++ln) {
                        mma_bf16(accA[ln][0], accA[ln][1], accA[ln][2], accA[ln][3],
                                 ah[0], ah[1], ah[2], ah[3], bh[2*ln], bh[2*ln+1]);
                        mma_bf16(accB[ln][0], accB[ln][1], accB[ln][2], accB[ln][3],
                                 ah[0], ah[1], ah[2], ah[3], bl[2*ln], bl[2*ln+1]);
                        mma_bf16(accC[ln][0], accC[ln][1], accC[ln][2], accC[ln][3],
                                 al[0], al[1], al[2], al[3], bh[2*ln], bh[2*ln+1]);
                    }
                }
                __syncthreads();
            }
        }

        // ========== switch to solve-phase smem (aliases GEMM tiles) ==========
        // epilogue: summed fragments -> up (d0,d1 at (r,2c), d2,d3 at (r+8,2c))
        {
            float* up = (float*)(smem + UP_OFF);
            const int er = wrow * 16 + (lane >> 2);
            const int ec = wcol * 32 + 2 * (lane & 3);
            #pragma unroll
            for (int ln = 0; ln < 4; ++ln) {
                float2 v0, v1;
                v0.x = accA[ln][0] + accB[ln][0] + accC[ln][0];
                v0.y = accA[ln][1] + accB[ln][1] + accC[ln][1];
                v1.x = accA[ln][2] + accB[ln][2] + accC[ln][2];
                v1.y = accA[ln][3] + accB[ln][3] + accC[ln][3];
                *(float2*)&up[er * AR + ec + ln * 8]       = v0;
                *(float2*)&up[(er + 8) * AR + ec + ln * 8] = v1;
            }
        }
        // diagonal block, transposed + strictly-lower masked
        {
            float* diag = (float*)(smem + DIAG_OFF);
            const int jj  = tid & 63;
            const int ig0 = (tid >> 6) * 16;
            const float* src = A + (size_t)(j0 + jj) * K_DIM + j0 + ig0;
            #pragma unroll
            for (int q = 0; q < 4; ++q) {
                const float4 r = *(const float4*)(src + 4 * q);
                const int i = ig0 + 4 * q;
                diag[(i + 0) * AR + jj] = (i + 0 < jj) ? r.x : 0.0f;
                diag[(i + 1) * AR + jj] = (i + 1 < jj) ? r.y : 0.0f;
                diag[(i + 2) * AR + jj] = (i + 2 < jj) ? r.z : 0.0f;
                diag[(i + 3) * AR + jj] = (i + 3 < jj) ? r.w : 0.0f;
            }
        }
        __syncthreads();

        // ======= in-panel sequential micro-solve: thread b owns a sample =====
        if (tid < BT) {
            float ul[PP];
            const float* up = (const float*)(smem + UP_OFF);
            const float* diag = (const float*)(smem + DIAG_OFF);
            const float* zp = z + (size_t)(b0 + tid) * K_DIM + j0;
            #pragma unroll
            for (int q = 0; q < 16; ++q) {
                const float4 zq = *(const float4*)(zp + 4 * q);
                const float4 aq = *(const float4*)&up[tid * AR + 4 * q];
                ul[4*q+0] = aq.x + zq.x;
                ul[4*q+1] = aq.y + zq.y;
                ul[4*q+2] = aq.z + zq.z;
                ul[4*q+3] = aq.w + zq.w;
            }
            const int jrel = t_abs - j0;
            #pragma unroll
            for (int i = 0; i < PP; ++i) {
                const float val = (jrel == i) ? vint : ul[i];
                ul[i] = val;
                #pragma unroll
                for (int q = (i >> 2); q < 16; ++q) {
                    const float4 d = *(const float4*)&diag[i * AR + 4 * q];
                    ul[4*q+0] = fmaf(d.x, val, ul[4*q+0]);
                    ul[4*q+1] = fmaf(d.y, val, ul[4*q+1]);
                    ul[4*q+2] = fmaf(d.z, val, ul[4*q+2]);
                    ul[4*q+3] = fmaf(d.w, val, ul[4*q+3]);
                }
            }
            // fp32 output
            float* op = out + (size_t)(b0 + tid) * K_DIM + j0;
            #pragma unroll
            for (int q = 0; q < 16; ++q) {
                float4 v; v.x = ul[4*q+0]; v.y = ul[4*q+1]; v.z = ul[4*q+2]; v.w = ul[4*q+3];
                *(float4*)(op + 4 * q) = v;
            }
            // bf16 hi/lo scratch for later panels' GEMMs
            __nv_bfloat16* uh  = g_uhi + (size_t)(b0 + tid) * K_DIM + j0;
            __nv_bfloat16* ulp = g_ulo + (size_t)(b0 + tid) * K_DIM + j0;
            #pragma unroll
            for (int q = 0; q < 8; ++q) {
                union { __nv_bfloat16 v[8]; uint4 u; } ph, pl;
                #pragma unroll
                for (int j = 0; j < 8; ++j) {
                    const float x = ul[8*q + j];
                    const __nv_bfloat16 h = __float2bfloat16(x);
                    ph.v[j] = h;
                    pl.v[j] = __float2bfloat16(x - __bfloat162float(h));
                }
                *(uint4*)(uh  + 8 * q) = ph.u;
                *(uint4*)(ulp + 8 * q) = pl.u;
            }
        }
        __syncthreads();   // scratch + smem reuse ordered before next panel
    }
}

extern "C" void kernel_launch(void* const* d_in, const int* in_sizes, int n_in,
                              void* d_out, int out_size) {
    const float* z     = (const float*)d_in[0];
    const int*   tgt   = (const int*)  d_in[1];
    const int*   vari  = (const int*)  d_in[2];
    const float* A     = (const float*)d_in[3];
    const float* means = (const float*)d_in[4];
    const float* logsc = (const float*)d_in[5];
    float* out = (float*)d_out;
    (void)in_sizes; (void)n_in; (void)out_size;

    cudaFuncSetAttribute(scm_kernel, cudaFuncAttributeMaxDynamicSharedMemorySize, SM_BYTES);
    prep_kernel<<<(K_DIM * K_DIM) / 256, 256>>>(A);
    scm_kernel<<<B_SZ / BT, NTH, SM_BYTES>>>(z, tgt, vari, A, means, logsc, out);
}